// round 2
// baseline (speedup 1.0000x reference)
#include <cuda_runtime.h>
#include <math.h>

// Problem dimensions (fixed by the dataset)
#define SS 512   // timesteps
#define BB 128   // batch
#define DD 256   // input dim
#define HH 512   // hidden
#define GG 2048  // 4*H (gate-interleaved: col n = j*4 + gate)
#define BH (BB*HH)

// Device scratch (no runtime allocation allowed)
__device__ float g_U[HH*GG];               // interleaved U' [512][2048]
__device__ float g_W[DD*GG];               // interleaved W' [256][2048]
__device__ float g_bias[GG];               // interleaved bias [2048]
__device__ float g_mdhp[BH];               // tanh(alpha@A - (beta*ts)@B + theta@C)
__device__ float g_c[BH];                  // running cell state
__device__ float g_xw[(size_t)SS*BB*GG];   // precomputed x@W' + b  (512 MB)

// ---------------------------------------------------------------------------
// Build gate-interleaved W', U', bias
// ---------------------------------------------------------------------------
__global__ void prep_weights(const float* __restrict__ Wi, const float* __restrict__ Ui, const float* __restrict__ bi,
                             const float* __restrict__ Wf, const float* __restrict__ Uf, const float* __restrict__ bf,
                             const float* __restrict__ Wc, const float* __restrict__ Uc, const float* __restrict__ bc,
                             const float* __restrict__ Wo, const float* __restrict__ Uo, const float* __restrict__ bo)
{
    int idx = blockIdx.x * blockDim.x + threadIdx.x;
    int stride = gridDim.x * blockDim.x;
    for (int i = idx; i < HH * GG; i += stride) {
        int k = i / GG;
        int n = i % GG;
        int j = n >> 2;
        int g = n & 3;
        const float* U = (g == 0) ? Ui : (g == 1) ? Uf : (g == 2) ? Uc : Uo;
        g_U[i] = U[k * HH + j];
        if (i < DD * GG) {
            const float* W = (g == 0) ? Wi : (g == 1) ? Wf : (g == 2) ? Wc : Wo;
            g_W[i] = W[k * HH + j];
        }
        if (i < GG) {
            const float* bptr = (g == 0) ? bi : (g == 1) ? bf : (g == 2) ? bc : bo;
            g_bias[i] = bptr[j];
        }
    }
}

// ---------------------------------------------------------------------------
// mdhp = tanh(alpha @ A - (beta*tspan) @ B + theta @ C)   [B,H]
// one block per batch row, 512 threads = H columns
// ---------------------------------------------------------------------------
__global__ void mdhp_kernel(const float* __restrict__ alpha, const float* __restrict__ beta,
                            const float* __restrict__ theta, const float* __restrict__ tspan,
                            const float* __restrict__ A, const float* __restrict__ Bm,
                            const float* __restrict__ C)
{
    int b = blockIdx.x;
    int j = threadIdx.x;   // 0..511
    __shared__ float sa[256], sb[256], st[16];
    float ts = tspan[b];
    if (j < 256) {
        sa[j] = alpha[b * 256 + j];
        sb[j] = beta[b * 256 + j] * ts;
    }
    if (j < 16) st[j] = theta[b * 16 + j];
    __syncthreads();
    float acc = 0.f;
    #pragma unroll 4
    for (int k = 0; k < 256; k++)
        acc += sa[k] * A[k * 512 + j] - sb[k] * Bm[k * 512 + j];
    #pragma unroll
    for (int k = 0; k < 16; k++)
        acc += st[k] * C[k * 512 + j];
    g_mdhp[b * 512 + j] = tanhf(acc);
}

__global__ void init_c(const float* __restrict__ c0)
{
    int i = blockIdx.x * blockDim.x + threadIdx.x;
    if (i < BH) g_c[i] = c0[i];
}

// ---------------------------------------------------------------------------
// xW GEMM: [65536 x 256] @ [256 x 2048] + bias -> g_xw (interleaved cols)
// 64x64 tile, BK=16, 256 threads, 4x4 register tile
// ---------------------------------------------------------------------------
#define XBM 64
#define XBN 64
#define XBK 16
__global__ __launch_bounds__(256) void xw_gemm(const float* __restrict__ x)
{
    __shared__ float As[XBK][XBM];
    __shared__ float Bs[XBK][XBN];
    int n0 = blockIdx.x * XBN;
    int m0 = blockIdx.y * XBM;
    int tid = threadIdx.x;
    int tcol = tid & 15;   // 0..15 -> 4 cols each
    int trow = tid >> 4;   // 0..15 -> 4 rows each
    float acc[4][4] = {};

    for (int k0 = 0; k0 < DD; k0 += XBK) {
        {   // load A tile (transposed): As[kk][r] = x[(m0+r)*DD + k0+kk]
            int r   = tid >> 2;          // 0..63
            int kk0 = (tid & 3) << 2;    // 0,4,8,12
            float4 v = *(const float4*)&x[(size_t)(m0 + r) * DD + k0 + kk0];
            As[kk0 + 0][r] = v.x; As[kk0 + 1][r] = v.y;
            As[kk0 + 2][r] = v.z; As[kk0 + 3][r] = v.w;
        }
        {   // load B tile
            int kk = tid >> 4;           // 0..15
            int c0 = (tid & 15) << 2;    // 0..60
            *(float4*)&Bs[kk][c0] = *(const float4*)&g_W[(size_t)(k0 + kk) * GG + n0 + c0];
        }
        __syncthreads();
        #pragma unroll
        for (int kk = 0; kk < XBK; kk++) {
            float4 a = *(const float4*)&As[kk][trow << 2];
            float4 b = *(const float4*)&Bs[kk][tcol << 2];
            float av[4] = {a.x, a.y, a.z, a.w};
            float bv[4] = {b.x, b.y, b.z, b.w};
            #pragma unroll
            for (int i2 = 0; i2 < 4; i2++)
                #pragma unroll
                for (int j2 = 0; j2 < 4; j2++)
                    acc[i2][j2] = fmaf(av[i2], bv[j2], acc[i2][j2]);
        }
        __syncthreads();
    }

    float4 b4 = *(const float4*)&g_bias[n0 + (tcol << 2)];
    #pragma unroll
    for (int i2 = 0; i2 < 4; i2++) {
        int m = m0 + (trow << 2) + i2;
        float4 o4 = make_float4(acc[i2][0] + b4.x, acc[i2][1] + b4.y,
                                acc[i2][2] + b4.z, acc[i2][3] + b4.w);
        *(float4*)&g_xw[(size_t)m * GG + n0 + (tcol << 2)] = o4;
    }
}

// ---------------------------------------------------------------------------
// One LSTM step: g = h_prev @ U' + xw[t]; gates; c,h update.
// Tile: 32 rows x 64 interleaved cols (= 16 h-cols, all 4 gates), K=512.
// 128 threads, 4x4 register tile. grid = (2048/64, 128/32) = (32, 4) = 128 blocks.
// ---------------------------------------------------------------------------
#define TBM 32
#define TBN 64
#define TBK 16
__global__ __launch_bounds__(128) void lstm_step(const float* __restrict__ hprev,
                                                 float* __restrict__ out, int t)
{
    __shared__ float hs[TBK][TBM];
    __shared__ float us[TBK][TBN];
    __shared__ float gsm[TBM][TBN];
    int n0 = blockIdx.x * TBN;
    int b0 = blockIdx.y * TBM;
    int tid = threadIdx.x;
    int tcol = tid & 15;   // 0..15 -> 4 cols
    int trow = tid >> 4;   // 0..7  -> 4 rows
    float acc[4][4] = {};

    for (int k0 = 0; k0 < HH; k0 += TBK) {
        {   // h tile (transposed load)
            int r   = tid >> 2;          // 0..31
            int kk0 = (tid & 3) << 2;    // 0,4,8,12
            float4 v = *(const float4*)&hprev[(size_t)(b0 + r) * HH + k0 + kk0];
            hs[kk0 + 0][r] = v.x; hs[kk0 + 1][r] = v.y;
            hs[kk0 + 2][r] = v.z; hs[kk0 + 3][r] = v.w;
        }
        {   // U tile: 16x64 floats, 2 float4 per thread
            int kk = tid >> 4;           // 0..7
            int c0 = (tid & 15) << 2;
            *(float4*)&us[kk][c0]     = *(const float4*)&g_U[(size_t)(k0 + kk) * GG + n0 + c0];
            *(float4*)&us[kk + 8][c0] = *(const float4*)&g_U[(size_t)(k0 + kk + 8) * GG + n0 + c0];
        }
        __syncthreads();
        #pragma unroll
        for (int kk = 0; kk < TBK; kk++) {
            float4 a = *(const float4*)&hs[kk][trow << 2];
            float4 b = *(const float4*)&us[kk][tcol << 2];
            float av[4] = {a.x, a.y, a.z, a.w};
            float bv[4] = {b.x, b.y, b.z, b.w};
            #pragma unroll
            for (int i2 = 0; i2 < 4; i2++)
                #pragma unroll
                for (int j2 = 0; j2 < 4; j2++)
                    acc[i2][j2] = fmaf(av[i2], bv[j2], acc[i2][j2]);
        }
        __syncthreads();
    }

    // add precomputed xW(t) and stage the gate tile in smem
    #pragma unroll
    for (int i2 = 0; i2 < 4; i2++) {
        int r = (trow << 2) + i2;  // 0..31
        const float4 xw4 = *(const float4*)&g_xw[((size_t)t * BB + b0 + r) * GG + n0 + (tcol << 2)];
        float4 o4 = make_float4(acc[i2][0] + xw4.x, acc[i2][1] + xw4.y,
                                acc[i2][2] + xw4.z, acc[i2][3] + xw4.w);
        *(float4*)&gsm[r][tcol << 2] = o4;
    }
    __syncthreads();

    // gate math: 32 rows x 16 h-cols = 512 elements, 4 per thread
    #pragma unroll
    for (int q = 0; q < 4; q++) {
        int p  = q * 128 + tid;        // 0..511
        int r  = p >> 4;               // 0..31
        int jl = p & 15;               // 0..15
        float gi = gsm[r][jl * 4 + 0];
        float gf = gsm[r][jl * 4 + 1];
        float gc = gsm[r][jl * 4 + 2];
        float go = gsm[r][jl * 4 + 3];
        int bglob = b0 + r;
        int jglob = (n0 >> 2) + jl;
        int idx = bglob * HH + jglob;
        float cold = g_c[idx];
        float md   = g_mdhp[idx];
        float it = 1.f / (1.f + __expf(-gi));
        float ft = 1.f / (1.f + __expf(-gf));
        float ch = tanhf(gc);
        float ot = 1.f / (1.f + __expf(-go));
        float cn = md * (ft * cold + it * ch);
        g_c[idx] = cn;
        out[(size_t)t * BH + idx] = ot * tanhf(cn);
    }
}

// copy h_T (== outputs[S-1]) and c_T into the output tail
__global__ void finalize(float* __restrict__ out)
{
    int i = blockIdx.x * blockDim.x + threadIdx.x;
    if (i < BH) {
        out[(size_t)SS * BH + i]      = out[(size_t)(SS - 1) * BH + i];
        out[(size_t)SS * BH + BH + i] = g_c[i];
    }
}

// ---------------------------------------------------------------------------
extern "C" void kernel_launch(void* const* d_in, const int* in_sizes, int n_in,
                              void* d_out, int out_size)
{
    const float* x     = (const float*)d_in[0];
    const float* h0    = (const float*)d_in[1];
    const float* c0    = (const float*)d_in[2];
    const float* alpha = (const float*)d_in[3];
    const float* beta  = (const float*)d_in[4];
    const float* theta = (const float*)d_in[5];
    const float* tspan = (const float*)d_in[6];
    const float* A     = (const float*)d_in[7];
    const float* Bm    = (const float*)d_in[8];
    const float* C     = (const float*)d_in[9];
    const float* Wi = (const float*)d_in[10];
    const float* Ui = (const float*)d_in[11];
    const float* bi = (const float*)d_in[12];
    const float* Wf = (const float*)d_in[13];
    const float* Uf = (const float*)d_in[14];
    const float* bf = (const float*)d_in[15];
    const float* Wc = (const float*)d_in[16];
    const float* Uc = (const float*)d_in[17];
    const float* bc = (const float*)d_in[18];
    const float* Wo = (const float*)d_in[19];
    const float* Uo = (const float*)d_in[20];
    const float* bo = (const float*)d_in[21];
    float* out = (float*)d_out;

    prep_weights<<<1024, 256>>>(Wi, Ui, bi, Wf, Uf, bf, Wc, Uc, bc, Wo, Uo, bo);
    mdhp_kernel<<<BB, 512>>>(alpha, beta, theta, tspan, A, Bm, C);
    init_c<<<(BH + 255) / 256, 256>>>(c0);
    xw_gemm<<<dim3(GG / XBN, (SS * BB) / XBM), 256>>>(x);

    for (int t = 0; t < SS; t++) {
        const float* hp = (t == 0) ? h0 : (out + (size_t)(t - 1) * BH);
        lstm_step<<<dim3(GG / TBN, BB / TBM), 128>>>(hp, out, t);
    }
    finalize<<<(BH + 255) / 256, 256>>>(out);
}

// round 3
// speedup vs baseline: 1.1058x; 1.1058x over previous
#include <cuda_runtime.h>
#include <math.h>

// Problem dimensions (fixed by the dataset)
#define SS 512   // timesteps
#define BB 128   // batch
#define DD 256   // input dim
#define HH 512   // hidden
#define GG 2048  // 4*H (gate-interleaved: col n = j*4 + gate)
#define BH (BB*HH)
#define NBLK 128 // persistent grid size (must be <= 148 for residency)

// Device scratch (no runtime allocation allowed)
__device__ float g_U[HH*GG];               // interleaved U' [512][2048]
__device__ float g_W[DD*GG];               // interleaved W' [256][2048]
__device__ float g_bias[GG];               // interleaved bias [2048]
__device__ float g_mdhp[BH];               // tanh(alpha@A - (beta*ts)@B + theta@C)
__device__ float g_c[BH];                  // final cell state (for finalize)
__device__ float g_xw[(size_t)SS*BB*GG];   // precomputed x@W' + b  (512 MB)
__device__ unsigned g_ctr;                 // grid-barrier counter

// ---------------------------------------------------------------------------
// Build gate-interleaved W', U', bias
// ---------------------------------------------------------------------------
__global__ void prep_weights(const float* __restrict__ Wi, const float* __restrict__ Ui, const float* __restrict__ bi,
                             const float* __restrict__ Wf, const float* __restrict__ Uf, const float* __restrict__ bf,
                             const float* __restrict__ Wc, const float* __restrict__ Uc, const float* __restrict__ bc,
                             const float* __restrict__ Wo, const float* __restrict__ Uo, const float* __restrict__ bo)
{
    int idx = blockIdx.x * blockDim.x + threadIdx.x;
    int stride = gridDim.x * blockDim.x;
    for (int i = idx; i < HH * GG; i += stride) {
        int k = i / GG;
        int n = i % GG;
        int j = n >> 2;
        int g = n & 3;
        const float* U = (g == 0) ? Ui : (g == 1) ? Uf : (g == 2) ? Uc : Uo;
        g_U[i] = U[k * HH + j];
        if (i < DD * GG) {
            const float* W = (g == 0) ? Wi : (g == 1) ? Wf : (g == 2) ? Wc : Wo;
            g_W[i] = W[k * HH + j];
        }
        if (i < GG) {
            const float* bptr = (g == 0) ? bi : (g == 1) ? bf : (g == 2) ? bc : bo;
            g_bias[i] = bptr[j];
        }
    }
}

// ---------------------------------------------------------------------------
// mdhp = tanh(alpha @ A - (beta*tspan) @ B + theta @ C)   [B,H]
// ---------------------------------------------------------------------------
__global__ void mdhp_kernel(const float* __restrict__ alpha, const float* __restrict__ beta,
                            const float* __restrict__ theta, const float* __restrict__ tspan,
                            const float* __restrict__ A, const float* __restrict__ Bm,
                            const float* __restrict__ C)
{
    int b = blockIdx.x;
    int j = threadIdx.x;   // 0..511
    __shared__ float sa[256], sb[256], st[16];
    float ts = tspan[b];
    if (j < 256) {
        sa[j] = alpha[b * 256 + j];
        sb[j] = beta[b * 256 + j] * ts;
    }
    if (j < 16) st[j] = theta[b * 16 + j];
    __syncthreads();
    float acc = 0.f;
    #pragma unroll 4
    for (int k = 0; k < 256; k++)
        acc += sa[k] * A[k * 512 + j] - sb[k] * Bm[k * 512 + j];
    #pragma unroll
    for (int k = 0; k < 16; k++)
        acc += st[k] * C[k * 512 + j];
    g_mdhp[b * 512 + j] = tanhf(acc);
}

__global__ void reset_ctr() { g_ctr = 0u; }

// ---------------------------------------------------------------------------
// xW GEMM: [65536 x 256] @ [256 x 2048] + bias -> g_xw (interleaved cols)
// 128x64 tile, BK=16, 256 threads, 8x4 register tile
// ---------------------------------------------------------------------------
#define XBM 128
#define XBN 64
#define XBK 16
#define APAD 136
#define BPAD 68
__global__ __launch_bounds__(256, 2) void xw_gemm(const float* __restrict__ x)
{
    __shared__ __align__(16) float As[XBK][APAD];
    __shared__ __align__(16) float Bs[XBK][BPAD];
    int n0 = blockIdx.x * XBN;
    int m0 = blockIdx.y * XBM;
    int tid = threadIdx.x;
    int tcol = tid & 15;   // 16 -> 4 cols each
    int trow = tid >> 4;   // 16 -> 8 rows each
    float acc[8][4] = {};

    for (int k0 = 0; k0 < DD; k0 += XBK) {
        #pragma unroll
        for (int j = 0; j < 2; j++) {   // A tile: transposed store
            int u = tid * 2 + j;        // 0..511 float4 slots
            int r = u >> 2;             // 0..127
            int ks = (u & 3) << 2;      // 0,4,8,12
            float4 v = *(const float4*)&x[(size_t)(m0 + r) * DD + k0 + ks];
            As[ks + 0][r] = v.x; As[ks + 1][r] = v.y;
            As[ks + 2][r] = v.z; As[ks + 3][r] = v.w;
        }
        {   // B tile
            int kk = tid >> 4;
            int c  = (tid & 15) << 2;
            *(float4*)&Bs[kk][c] = *(const float4*)&g_W[(size_t)(k0 + kk) * GG + n0 + c];
        }
        __syncthreads();
        #pragma unroll
        for (int kk = 0; kk < XBK; kk++) {
            float4 a0 = *(const float4*)&As[kk][trow * 8];
            float4 a1 = *(const float4*)&As[kk][trow * 8 + 4];
            float4 b  = *(const float4*)&Bs[kk][tcol * 4];
            float av[8] = {a0.x, a0.y, a0.z, a0.w, a1.x, a1.y, a1.z, a1.w};
            float bv[4] = {b.x, b.y, b.z, b.w};
            #pragma unroll
            for (int i2 = 0; i2 < 8; i2++)
                #pragma unroll
                for (int j2 = 0; j2 < 4; j2++)
                    acc[i2][j2] = fmaf(av[i2], bv[j2], acc[i2][j2]);
        }
        __syncthreads();
    }

    float4 b4 = *(const float4*)&g_bias[n0 + (tcol << 2)];
    #pragma unroll
    for (int i2 = 0; i2 < 8; i2++) {
        int m = m0 + trow * 8 + i2;
        float4 o4 = make_float4(acc[i2][0] + b4.x, acc[i2][1] + b4.y,
                                acc[i2][2] + b4.z, acc[i2][3] + b4.w);
        *(float4*)&g_xw[(size_t)m * GG + n0 + (tcol << 2)] = o4;
    }
}

// ---------------------------------------------------------------------------
// Persistent LSTM recurrence.
// Grid: (64, 2) = 128 blocks (1/SM, all resident). 512 threads.
// Block tile: 64 batch rows x 32 interleaved cols (= 8 h-cols x 4 gates).
// U slice (512x32 = 64KB) lives in smem for all 512 steps.
// c and mdhp live in registers. h chains through `out` (outputs[t] == h_t).
// Software grid barrier between steps.
// ---------------------------------------------------------------------------
__global__ __launch_bounds__(512) void lstm_persist(const float* __restrict__ h0,
                                                    const float* __restrict__ c0,
                                                    float* __restrict__ out)
{
    extern __shared__ __align__(16) float sm[];
    float* us = sm;                 // [512][32] = 16384 floats
    float* hs = sm + 512 * 32;      // [2][32][64] = 4096 floats (double-buffered h chunk)

    const int tid  = threadIdx.x;
    const int n0   = blockIdx.x * 32;   // interleaved col base
    const int b0   = blockIdx.y * 64;   // batch row base
    const int tcol = tid & 15;          // 16 col-pairs -> 32 cols
    const int trow = tid >> 4;          // 32 row-pairs -> 64 rows
    const int lrow = tid >> 3;          // 64 load rows
    const int kseg = tid & 7;           // 8 k-segments of 4

    // Load persistent U slice: us[k*32 + c] = g_U[k*GG + n0 + c]
    for (int i = tid; i < 512 * 8; i += 512) {  // 4096 float4
        int k = i >> 3, c = (i & 7) << 2;
        *(float4*)&us[k * 32 + c] = *(const float4*)&g_U[(size_t)k * GG + n0 + c];
    }

    // c / mdhp in registers; 1 element per thread.
    const int pr  = tid >> 3;           // 0..63  (row within tile)
    const int pj  = tid & 7;            // 0..7   (h-col within tile)
    const int pidx = (b0 + pr) * HH + (n0 >> 2) + pj;
    float cr = c0[pidx];
    float mr = g_mdhp[pidx];
    __syncthreads();

    for (int t = 0; t < SS; t++) {
        const float* h = (t == 0) ? h0 : (out + (size_t)(t - 1) * BH);
        const float* hrow = h + (size_t)(b0 + lrow) * HH + kseg * 4;
        float acc[2][2] = {};

        // prologue: chunk 0
        float4 f = *(const float4*)&hrow[0];
        {
            float* dst = &hs[(kseg * 4) * 64 + lrow];
            dst[0 * 64] = f.x; dst[1 * 64] = f.y; dst[2 * 64] = f.z; dst[3 * 64] = f.w;
        }
        __syncthreads();

        #pragma unroll 1
        for (int cch = 0; cch < 16; cch++) {
            if (cch < 15)
                f = *(const float4*)&hrow[(cch + 1) * 32];
            const float* hb = &hs[(cch & 1) * 2048];
            const float* ub = &us[cch * 1024];
            #pragma unroll
            for (int kk = 0; kk < 32; kk++) {
                float2 a = *(const float2*)&hb[kk * 64 + trow * 2];
                float2 b = *(const float2*)&ub[kk * 32 + tcol * 2];
                acc[0][0] = fmaf(a.x, b.x, acc[0][0]);
                acc[0][1] = fmaf(a.x, b.y, acc[0][1]);
                acc[1][0] = fmaf(a.y, b.x, acc[1][0]);
                acc[1][1] = fmaf(a.y, b.y, acc[1][1]);
            }
            if (cch < 15) {
                float* dst = &hs[((cch + 1) & 1) * 2048 + (kseg * 4) * 64 + lrow];
                dst[0 * 64] = f.x; dst[1 * 64] = f.y; dst[2 * 64] = f.z; dst[3 * 64] = f.w;
            }
            __syncthreads();
        }

        // add xW(t), stage gate tile into hs buffer 0 (64 rows x 32 cols)
        {
            const float* xwp = g_xw + ((size_t)t * BB + b0 + trow * 2) * GG + n0 + tcol * 2;
            float* gsm = hs;
            #pragma unroll
            for (int i = 0; i < 2; i++) {
                float2 xw = *(const float2*)&xwp[(size_t)i * GG];
                gsm[(trow * 2 + i) * 32 + tcol * 2 + 0] = acc[i][0] + xw.x;
                gsm[(trow * 2 + i) * 32 + tcol * 2 + 1] = acc[i][1] + xw.y;
            }
        }
        __syncthreads();

        // gate math: 1 h-element per thread
        {
            float4 g4 = *(const float4*)&hs[pr * 32 + pj * 4];
            float it = 1.f / (1.f + __expf(-g4.x));
            float ft = 1.f / (1.f + __expf(-g4.y));
            float ch = tanhf(g4.z);
            float ot = 1.f / (1.f + __expf(-g4.w));
            float cn = mr * (ft * cr + it * ch);
            cr = cn;
            out[(size_t)t * BH + pidx] = ot * tanhf(cn);
        }
        __syncthreads();

        // grid barrier: release (fence + atomic), acquire (spin + fence)
        if (tid == 0) {
            __threadfence();
            atomicAdd(&g_ctr, 1u);
            unsigned target = (unsigned)(t + 1) * (unsigned)NBLK;
            while (*(volatile unsigned*)&g_ctr < target) { }
            __threadfence();
        }
        __syncthreads();
    }

    // persist final c for finalize
    g_c[pidx] = cr;
}

// copy h_T (== outputs[S-1]) and c_T into the output tail
__global__ void finalize(float* __restrict__ out)
{
    int i = blockIdx.x * blockDim.x + threadIdx.x;
    if (i < BH) {
        out[(size_t)SS * BH + i]      = out[(size_t)(SS - 1) * BH + i];
        out[(size_t)SS * BH + BH + i] = g_c[i];
    }
}

// ---------------------------------------------------------------------------
extern "C" void kernel_launch(void* const* d_in, const int* in_sizes, int n_in,
                              void* d_out, int out_size)
{
    const float* x     = (const float*)d_in[0];
    const float* h0    = (const float*)d_in[1];
    const float* c0    = (const float*)d_in[2];
    const float* alpha = (const float*)d_in[3];
    const float* beta  = (const float*)d_in[4];
    const float* theta = (const float*)d_in[5];
    const float* tspan = (const float*)d_in[6];
    const float* A     = (const float*)d_in[7];
    const float* Bm    = (const float*)d_in[8];
    const float* C     = (const float*)d_in[9];
    const float* Wi = (const float*)d_in[10];
    const float* Ui = (const float*)d_in[11];
    const float* bi = (const float*)d_in[12];
    const float* Wf = (const float*)d_in[13];
    const float* Uf = (const float*)d_in[14];
    const float* bf = (const float*)d_in[15];
    const float* Wc = (const float*)d_in[16];
    const float* Uc = (const float*)d_in[17];
    const float* bc = (const float*)d_in[18];
    const float* Wo = (const float*)d_in[19];
    const float* Uo = (const float*)d_in[20];
    const float* bo = (const float*)d_in[21];
    float* out = (float*)d_out;

    const int SMEM = (512 * 32 + 2 * 32 * 64) * sizeof(float);  // 81920 B
    cudaFuncSetAttribute(lstm_persist, cudaFuncAttributeMaxDynamicSharedMemorySize, SMEM);

    prep_weights<<<1024, 256>>>(Wi, Ui, bi, Wf, Uf, bf, Wc, Uc, bc, Wo, Uo, bo);
    mdhp_kernel<<<BB, 512>>>(alpha, beta, theta, tspan, A, Bm, C);
    reset_ctr<<<1, 1>>>();
    xw_gemm<<<dim3(GG / XBN, (SS * BB) / XBM), 256>>>(x);
    lstm_persist<<<dim3(64, 2), 512, SMEM>>>(h0, c0, out);
    finalize<<<(BH + 255) / 256, 256>>>(out);
}

// round 4
// speedup vs baseline: 1.6746x; 1.5144x over previous
#include <cuda_runtime.h>
#include <math.h>

// Problem dimensions (fixed by the dataset)
#define SS 512   // timesteps
#define BB 128   // batch
#define DD 256   // input dim
#define HH 512   // hidden
#define GG 2048  // 4*H (gate-interleaved: col n = j*4 + gate)
#define BH (BB*HH)

// Device scratch (no runtime allocation allowed)
__device__ float g_U[HH*GG];               // interleaved U' [512][2048]
__device__ float g_W[DD*GG];               // interleaved W' [256][2048]
__device__ float g_bias[GG];               // interleaved bias [2048]
__device__ float g_mdhp[BH];               // tanh(alpha@A - (beta*ts)@B + theta@C)
__device__ float g_c[BH];                  // final cell state (for finalize)
__device__ float g_xw[(size_t)SS*BB*GG];   // precomputed x@W' + b  (512 MB)
__device__ float g_hT[2*HH*BB];            // double-buffered transposed h: [2][512 k][128 b]
__device__ unsigned g_ctr4[4];             // per-rowgroup barrier counters

// ---------------------------------------------------------------------------
// Build gate-interleaved W', U', bias
// ---------------------------------------------------------------------------
__global__ void prep_weights(const float* __restrict__ Wi, const float* __restrict__ Ui, const float* __restrict__ bi,
                             const float* __restrict__ Wf, const float* __restrict__ Uf, const float* __restrict__ bf,
                             const float* __restrict__ Wc, const float* __restrict__ Uc, const float* __restrict__ bc,
                             const float* __restrict__ Wo, const float* __restrict__ Uo, const float* __restrict__ bo)
{
    int idx = blockIdx.x * blockDim.x + threadIdx.x;
    int stride = gridDim.x * blockDim.x;
    for (int i = idx; i < HH * GG; i += stride) {
        int k = i / GG;
        int n = i % GG;
        int j = n >> 2;
        int g = n & 3;
        const float* U = (g == 0) ? Ui : (g == 1) ? Uf : (g == 2) ? Uc : Uo;
        g_U[i] = U[k * HH + j];
        if (i < DD * GG) {
            const float* W = (g == 0) ? Wi : (g == 1) ? Wf : (g == 2) ? Wc : Wo;
            g_W[i] = W[k * HH + j];
        }
        if (i < GG) {
            const float* bptr = (g == 0) ? bi : (g == 1) ? bf : (g == 2) ? bc : bo;
            g_bias[i] = bptr[j];
        }
    }
}

// ---------------------------------------------------------------------------
// mdhp = tanh(alpha @ A - (beta*tspan) @ B + theta @ C)   [B,H]
// ---------------------------------------------------------------------------
__global__ void mdhp_kernel(const float* __restrict__ alpha, const float* __restrict__ beta,
                            const float* __restrict__ theta, const float* __restrict__ tspan,
                            const float* __restrict__ A, const float* __restrict__ Bm,
                            const float* __restrict__ C)
{
    int b = blockIdx.x;
    int j = threadIdx.x;   // 0..511
    __shared__ float sa[256], sb[256], st[16];
    float ts = tspan[b];
    if (j < 256) {
        sa[j] = alpha[b * 256 + j];
        sb[j] = beta[b * 256 + j] * ts;
    }
    if (j < 16) st[j] = theta[b * 16 + j];
    __syncthreads();
    float acc = 0.f;
    #pragma unroll 4
    for (int k = 0; k < 256; k++)
        acc += sa[k] * A[k * 512 + j] - sb[k] * Bm[k * 512 + j];
    #pragma unroll
    for (int k = 0; k < 16; k++)
        acc += st[k] * C[k * 512 + j];
    g_mdhp[b * 512 + j] = tanhf(acc);
}

// zero barrier counters + transpose h0 into g_hT buffer 0
__global__ void prep_state(const float* __restrict__ h0)
{
    int i = blockIdx.x * blockDim.x + threadIdx.x;
    if (i < 4) g_ctr4[i] = 0u;
    if (i < HH * BB) {
        int k = i >> 7;        // 0..511
        int b = i & 127;       // 0..127
        g_hT[i] = h0[b * HH + k];
    }
}

// ---------------------------------------------------------------------------
// xW GEMM: [65536 x 256] @ [256 x 2048] + bias -> g_xw (interleaved cols)
// 128x128 tile, BK=8, 256 threads, 8x8 register tile
// ---------------------------------------------------------------------------
__global__ __launch_bounds__(256, 2) void xw_gemm(const float* __restrict__ x)
{
    __shared__ __align__(16) float As[8][128];
    __shared__ __align__(16) float Bs[8][128];
    const int n0 = blockIdx.x * 128;
    const int m0 = blockIdx.y * 128;
    const int tid = threadIdx.x;
    const int tr = tid >> 4;    // 0..15
    const int tc = tid & 15;    // 0..15
    const int r0 = tr * 4;      // rows r0..r0+3 and r0+64..r0+67
    const int c0 = tc * 4;      // cols c0..c0+3 and c0+64..c0+67

    const int am = tid >> 1;            // A load row 0..127
    const int ak = (tid & 1) * 4;       // A load k offset 0 or 4
    const int bk = tid >> 5;            // B load k row 0..7
    const int bc = (tid & 31) * 4;      // B load col 0..124

    float acc[8][8] = {};
    float4 ra, rb;

    // prologue loads
    ra = *(const float4*)&x[(size_t)(m0 + am) * DD + ak];
    rb = *(const float4*)&g_W[(size_t)bk * GG + n0 + bc];

    for (int k0 = 0; k0 < DD; k0 += 8) {
        // stage regs -> smem
        As[ak + 0][am] = ra.x; As[ak + 1][am] = ra.y;
        As[ak + 2][am] = ra.z; As[ak + 3][am] = ra.w;
        *(float4*)&Bs[bk][bc] = rb;
        __syncthreads();

        // prefetch next tile
        if (k0 + 8 < DD) {
            ra = *(const float4*)&x[(size_t)(m0 + am) * DD + k0 + 8 + ak];
            rb = *(const float4*)&g_W[(size_t)(k0 + 8 + bk) * GG + n0 + bc];
        }

        #pragma unroll
        for (int kk = 0; kk < 8; kk++) {
            float4 a0 = *(const float4*)&As[kk][r0];
            float4 a1 = *(const float4*)&As[kk][r0 + 64];
            float4 b0 = *(const float4*)&Bs[kk][c0];
            float4 b1 = *(const float4*)&Bs[kk][c0 + 64];
            float av[8] = {a0.x, a0.y, a0.z, a0.w, a1.x, a1.y, a1.z, a1.w};
            float bv[8] = {b0.x, b0.y, b0.z, b0.w, b1.x, b1.y, b1.z, b1.w};
            #pragma unroll
            for (int i = 0; i < 8; i++)
                #pragma unroll
                for (int j = 0; j < 8; j++)
                    acc[i][j] = fmaf(av[i], bv[j], acc[i][j]);
        }
        __syncthreads();
    }

    float4 bb0 = *(const float4*)&g_bias[n0 + c0];
    float4 bb1 = *(const float4*)&g_bias[n0 + c0 + 64];
    #pragma unroll
    for (int i = 0; i < 8; i++) {
        int m = m0 + ((i < 4) ? (r0 + i) : (r0 + 60 + i));  // i>=4 -> r0+64+(i-4)
        float* orow = &g_xw[(size_t)m * GG + n0];
        float4 o0 = make_float4(acc[i][0] + bb0.x, acc[i][1] + bb0.y,
                                acc[i][2] + bb0.z, acc[i][3] + bb0.w);
        float4 o1 = make_float4(acc[i][4] + bb1.x, acc[i][5] + bb1.y,
                                acc[i][6] + bb1.z, acc[i][7] + bb1.w);
        *(float4*)&orow[c0]      = o0;
        *(float4*)&orow[c0 + 64] = o1;
    }
}

// ---------------------------------------------------------------------------
// Persistent LSTM recurrence.
// Grid: (32, 4) = 128 blocks (1/SM). 512 threads.
// Block tile: 32 batch rows x 64 interleaved cols (= 16 h-cols x 4 gates).
// U slice (512x64 = 128KB) persistent in smem. h read coalesced from g_hT
// (double-buffered, via ldcg). K-split-4 with smem partial reduction.
// Per-rowgroup software barrier (4 independent groups of 32 blocks).
// ---------------------------------------------------------------------------
__global__ __launch_bounds__(512) void lstm_persist(const float* __restrict__ c0,
                                                    float* __restrict__ out)
{
    extern __shared__ __align__(16) float sm[];
    float* us   = sm;                       // [512][64]  = 128KB
    float* hsT  = sm + 512 * 64;            // [512][32]  = 64KB  (k-major, conflict-free)
    float* part = sm + 512 * 64 + 512 * 32; // [16][512]  = 32KB  partial sums

    const int tid = threadIdx.x;
    const int bx  = blockIdx.x;            // 0..31 col block
    const int rg  = blockIdx.y;            // 0..3  row group
    const int n0  = bx * 64;
    const int b0  = rg * 32;

    // GEMM thread mapping: group g over K, 128 math threads per group, 4x4 tiles
    const int g   = tid >> 7;               // 0..3
    const int mt  = tid & 127;              // 0..127
    const int mr0 = (mt & 7) * 4;            // row base 0..28
    const int mc0 = (mt >> 3) * 4;           // col base 0..60
    const int kb  = g * 128;

    // loader mapping
    const int lr  = tid & 31;                // batch row lane
    const int lk0 = tid >> 5;                // 0..15

    // gate/reduce mapping: 1 h-element per thread
    const int pr  = tid >> 4;                // 0..31
    const int pj  = tid & 15;                // 0..15
    const int pmt = (pj << 3) | (pr >> 2);
    const int psub = (pr & 3) * 4;
    const int jglob = bx * 16 + pj;
    const int pidx = (b0 + pr) * HH + jglob;

    // Load persistent U slice
    for (int i = tid; i < 512 * 16; i += 512) {   // 8192 float4
        int k = i >> 4, c = (i & 15) << 2;
        *(float4*)&us[k * 64 + c] = *(const float4*)&g_U[(size_t)k * GG + n0 + c];
    }

    float cr = c0[pidx];
    float mr = g_mdhp[pidx];
    __syncthreads();

    for (int t = 0; t < SS; t++) {
        // ---- load transposed h tile (coalesced, L2-coherent) ----
        const float* hbuf = g_hT + (size_t)(t & 1) * (HH * BB);
        #pragma unroll 8
        for (int it = 0; it < 32; it++) {
            int k = lk0 + it * 16;
            hsT[k * 32 + lr] = __ldcg(&hbuf[k * BB + b0 + lr]);
        }
        // prefetch this thread's xw quad (DRAM) while GEMM runs
        float4 xw4 = *(const float4*)&g_xw[((size_t)t * BB + b0 + pr) * GG + n0 + pj * 4];
        __syncthreads();

        // ---- GEMM: 32x64 tile, this group's 128 K values ----
        float acc[4][4] = {};
        #pragma unroll 4
        for (int kk = 0; kk < 128; kk++) {
            int k = kb + kk;
            float4 a = *(const float4*)&hsT[k * 32 + mr0];
            float4 b = *(const float4*)&us[k * 64 + mc0];
            float av[4] = {a.x, a.y, a.z, a.w};
            float bv[4] = {b.x, b.y, b.z, b.w};
            #pragma unroll
            for (int i = 0; i < 4; i++)
                #pragma unroll
                for (int j = 0; j < 4; j++)
                    acc[i][j] = fmaf(av[i], bv[j], acc[i][j]);
        }

        // ---- write partials: part[(i*4+j)*512 + g*128 + mt] (bank = mt%32, conflict-free) ----
        #pragma unroll
        for (int i = 0; i < 4; i++)
            #pragma unroll
            for (int j = 0; j < 4; j++)
                part[(i * 4 + j) * 512 + (g << 7) + mt] = acc[i][j];
        __syncthreads();

        // ---- reduce over 4 groups + gates ----
        {
            float gq[4];
            #pragma unroll
            for (int q = 0; q < 4; q++) {
                const float* p = &part[(psub + q) * 512 + pmt];
                gq[q] = p[0] + p[128] + p[256] + p[384];
            }
            float gi = gq[0] + xw4.x;
            float gf = gq[1] + xw4.y;
            float gc = gq[2] + xw4.z;
            float go = gq[3] + xw4.w;
            float it_ = 1.f / (1.f + __expf(-gi));
            float ft  = 1.f / (1.f + __expf(-gf));
            float ch  = tanhf(gc);
            float ot  = 1.f / (1.f + __expf(-go));
            float cn  = mr * (ft * cr + it_ * ch);
            cr = cn;
            float hn = ot * tanhf(cn);
            out[(size_t)t * BH + pidx] = hn;
            g_hT[(size_t)((t + 1) & 1) * (HH * BB) + jglob * BB + b0 + pr] = hn;
        }

        // ---- per-rowgroup barrier ----
        __syncthreads();
        if (tid == 0) {
            __threadfence();
            atomicAdd(&g_ctr4[rg], 1u);
            unsigned target = (unsigned)(t + 1) * 32u;
            while (*(volatile unsigned*)&g_ctr4[rg] < target) { }
            __threadfence();
        }
        __syncthreads();
    }

    g_c[pidx] = cr;
}

// copy h_T (== outputs[S-1]) and c_T into the output tail
__global__ void finalize(float* __restrict__ out)
{
    int i = blockIdx.x * blockDim.x + threadIdx.x;
    if (i < BH) {
        out[(size_t)SS * BH + i]      = out[(size_t)(SS - 1) * BH + i];
        out[(size_t)SS * BH + BH + i] = g_c[i];
    }
}

// ---------------------------------------------------------------------------
extern "C" void kernel_launch(void* const* d_in, const int* in_sizes, int n_in,
                              void* d_out, int out_size)
{
    const float* x     = (const float*)d_in[0];
    const float* h0    = (const float*)d_in[1];
    const float* c0    = (const float*)d_in[2];
    const float* alpha = (const float*)d_in[3];
    const float* beta  = (const float*)d_in[4];
    const float* theta = (const float*)d_in[5];
    const float* tspan = (const float*)d_in[6];
    const float* A     = (const float*)d_in[7];
    const float* Bm    = (const float*)d_in[8];
    const float* C     = (const float*)d_in[9];
    const float* Wi = (const float*)d_in[10];
    const float* Ui = (const float*)d_in[11];
    const float* bi = (const float*)d_in[12];
    const float* Wf = (const float*)d_in[13];
    const float* Uf = (const float*)d_in[14];
    const float* bf = (const float*)d_in[15];
    const float* Wc = (const float*)d_in[16];
    const float* Uc = (const float*)d_in[17];
    const float* bc = (const float*)d_in[18];
    const float* Wo = (const float*)d_in[19];
    const float* Uo = (const float*)d_in[20];
    const float* bo = (const float*)d_in[21];
    float* out = (float*)d_out;

    const int SMEM = (512 * 64 + 512 * 32 + 16 * 512) * sizeof(float);  // 229376 B
    cudaFuncSetAttribute(lstm_persist, cudaFuncAttributeMaxDynamicSharedMemorySize, SMEM);

    prep_weights<<<1024, 256>>>(Wi, Ui, bi, Wf, Uf, bf, Wc, Uc, bc, Wo, Uo, bo);
    mdhp_kernel<<<BB, 512>>>(alpha, beta, theta, tspan, A, Bm, C);
    prep_state<<<(HH * BB + 255) / 256, 256>>>(h0);
    xw_gemm<<<dim3(GG / 128, (SS * BB) / 128), 256>>>(x);
    lstm_persist<<<dim3(32, 4), 512, SMEM>>>(c0, out);
    finalize<<<(BH + 255) / 256, 256>>>(out);
}